// round 6
// baseline (speedup 1.0000x reference)
#include <cuda_runtime.h>

#define T_STEPS 512
#define BATCH   64
#define HID     512
#define GATES3  1536
#define NB_REC  128
#define NT_REC  256
#define WP      540    // w row stride in floats (512 + 28 skew)
#define HT_SZ   6168   // hT floats (512*12 + skew + row)

// ---------------- scratch (static device allocations; no cudaMalloc) ----------------
__device__ float g_xg[(size_t)T_STEPS * BATCH * GATES3]; // precomputed input gates
__device__ float g_y0[(size_t)T_STEPS * BATCH * HID];    // layer-0 output
__device__ float g_hxT[2 * HID * BATCH];                 // h exchange, TRANSPOSED [parity][j][b]
__device__ unsigned g_flags[NB_REC];                     // per-block step flags
__device__ unsigned g_end_cnt[8];
__device__ volatile unsigned g_end_gen[8];

// ---------------- packed fp32x2 FMA (Blackwell FFMA2) ----------------
__device__ __forceinline__ float2 ffma2(float2 a, float2 b, float2 c) {
    float2 d;
    asm("fma.rn.f32x2 %0, %1, %2, %3;"
        : "=l"(reinterpret_cast<unsigned long long&>(d))
        : "l"(reinterpret_cast<unsigned long long&>(a)),
          "l"(reinterpret_cast<unsigned long long&>(b)),
          "l"(reinterpret_cast<unsigned long long&>(c)));
    return d;
}

__device__ __forceinline__ float sigmoidf_(float x) {
    return 1.f / (1.f + __expf(-x));
}

// ---------------- GEMM: out[M,N] = A[M,K] * W[N,K]^T + bias (R2 version, known-good) ----
__global__ void __launch_bounds__(256) gemm_bias_kernel(
    const float* __restrict__ A, const float* __restrict__ W,
    const float* __restrict__ bias, float* __restrict__ out, int K)
{
    __shared__ float As[16 * 132];
    __shared__ float Bs[16 * 132];

    const int tid = threadIdx.x;
    const int m0 = blockIdx.y * 128;
    const int n0 = blockIdx.x * 128;
    const int tm = tid >> 4;
    const int tn = tid & 15;

    float2 c2[8][4];
#pragma unroll
    for (int i = 0; i < 8; ++i)
#pragma unroll
        for (int p = 0; p < 4; ++p) c2[i][p] = make_float2(0.f, 0.f);

    for (int kt = 0; kt < K; kt += 16) {
#pragma unroll
        for (int u = 0; u < 2; ++u) {
            int s   = tid + u * 256;
            int row = s >> 2;
            int c4  = s & 3;
            float4 av = *(const float4*)(A + (size_t)(m0 + row) * K + kt + c4 * 4);
            As[(c4 * 4 + 0) * 132 + row] = av.x;
            As[(c4 * 4 + 1) * 132 + row] = av.y;
            As[(c4 * 4 + 2) * 132 + row] = av.z;
            As[(c4 * 4 + 3) * 132 + row] = av.w;
            float4 bv = *(const float4*)(W + (size_t)(n0 + row) * K + kt + c4 * 4);
            Bs[(c4 * 4 + 0) * 132 + row] = bv.x;
            Bs[(c4 * 4 + 1) * 132 + row] = bv.y;
            Bs[(c4 * 4 + 2) * 132 + row] = bv.z;
            Bs[(c4 * 4 + 3) * 132 + row] = bv.w;
        }
        __syncthreads();

#pragma unroll
        for (int kb = 0; kb < 16; ++kb) {
            float4 a0 = *(const float4*)(As + kb * 132 + tm * 8);
            float4 a1 = *(const float4*)(As + kb * 132 + tm * 8 + 4);
            float4 b0 = *(const float4*)(Bs + kb * 132 + tn * 8);
            float4 b1 = *(const float4*)(Bs + kb * 132 + tn * 8 + 4);
            float av[8] = {a0.x, a0.y, a0.z, a0.w, a1.x, a1.y, a1.z, a1.w};
            float2 bp[4] = {make_float2(b0.x, b0.y), make_float2(b0.z, b0.w),
                            make_float2(b1.x, b1.y), make_float2(b1.z, b1.w)};
#pragma unroll
            for (int i = 0; i < 8; ++i) {
                float2 as = make_float2(av[i], av[i]);
#pragma unroll
                for (int p = 0; p < 4; ++p) c2[i][p] = ffma2(as, bp[p], c2[i][p]);
            }
        }
        __syncthreads();
    }

    const float4 bb0 = *(const float4*)(bias + n0 + tn * 8);
    const float4 bb1 = *(const float4*)(bias + n0 + tn * 8 + 4);
#pragma unroll
    for (int i = 0; i < 8; ++i) {
        int m = m0 + tm * 8 + i;
        float4 o0 = make_float4(c2[i][0].x + bb0.x, c2[i][0].y + bb0.y,
                                c2[i][1].x + bb0.z, c2[i][1].y + bb0.w);
        float4 o1 = make_float4(c2[i][2].x + bb1.x, c2[i][2].y + bb1.y,
                                c2[i][3].x + bb1.z, c2[i][3].y + bb1.w);
        float* dst = out + (size_t)m * GATES3 + n0 + tn * 8;
        *(float4*)(dst)     = o0;
        *(float4*)(dst + 4) = o1;
    }
}

// ---------------- persistent GRU recurrence ----------------
// 128 blocks = 16 col-groups x 8 batch-groups.
// 256 threads = 32 cols x 8 k-splits. Thread tile: 1 col x 3 gates x 8 batches x K=64.
// h transposed in smem (hT[k][b], skewed); 8-way k-reduction through smem (reuses hT).
__global__ void __launch_bounds__(NT_REC, 1) gru_rec_kernel(
    const float* __restrict__ xg, const float* __restrict__ Whh,
    const float* __restrict__ bhh, float* __restrict__ y,
    float* __restrict__ hn_out)
{
    extern __shared__ float smem[];
    float* wS = smem;                 // 96 rows x 540 floats (k-skewed)
    float* hT = smem + 96 * WP;       // 6168 floats; reused as reduction buffer

    const int tid = threadIdx.x;
    const int bid = blockIdx.x;
    const int cg  = bid & 15;
    const int grp = bid >> 4;
    const int j0  = cg * 32;
    const int b0  = grp * 8;
    const int col = tid >> 3;        // 0..31
    const int ks  = tid & 7;         // 0..7 (k-split; doubles as batch index in finalize)
    const int j   = j0 + col;
    const int bb  = ks;              // finalize batch
    const int b   = b0 + bb;

    // one-time: W_hh slice into skewed smem: wS[row*WP + k + 4*(k>>6)]
    for (int idx = tid; idx < 96 * 512; idx += NT_REC) {
        int row = idx >> 9;
        int k   = idx & 511;
        int g   = row >> 5;
        int c   = row & 31;
        wS[row * WP + k + ((k >> 6) << 2)] =
            Whh[(size_t)(g * HID + j0 + c) * HID + k];
    }
    for (int idx = tid; idx < HT_SZ; idx += NT_REC) hT[idx] = 0.f;

    const float bhr = bhh[j];
    const float bhz = bhh[HID + j];
    const float bhn = bhh[2 * HID + j];

    const float* wp_r = wS + col * WP + ks * 68;           // ks*64 + 4*ks skew
    const float* wp_z = wp_r + 32 * WP;
    const float* wp_n = wp_r + 64 * WP;
    const float* hbase = hT + ks * 772;                    // ks*64*12 + 4*ks

    const size_t xofs = (size_t)b * GATES3 + j;
    float xr = xg[xofs];
    float xz = xg[xofs + HID];
    float xn = xg[xofs + 2 * HID];

    float hp = 0.f;   // own h (col, b) in regs
    __syncthreads();

    for (int t = 0; t < T_STEPS; ++t) {
        if (t > 0) {
            // group barrier: all 16 blocks of this group posted step t
            if (tid < 16) {
                const unsigned* fp = &g_flags[grp * 16 + tid];
                unsigned v;
                do {
                    asm volatile("ld.acquire.gpu.global.u32 %0, [%1];" : "=r"(v) : "l"(fp));
                } while (v < (unsigned)t);
            }
            __syncthreads();
            // stage h transposed: hT[jj][0..7] from g_hxT[jj][b0..b0+7]
            const float* hsrc = g_hxT + (size_t)(t & 1) * HID * BATCH;
            {
                int j1 = tid, j2 = tid + 256;
                float4 v0 = __ldcg((const float4*)(hsrc + j1 * BATCH + b0));
                float4 v1 = __ldcg((const float4*)(hsrc + j1 * BATCH + b0 + 4));
                float4 v2 = __ldcg((const float4*)(hsrc + j2 * BATCH + b0));
                float4 v3 = __ldcg((const float4*)(hsrc + j2 * BATCH + b0 + 4));
                int d1 = j1 * 12 + ((j1 >> 6) << 2);
                int d2 = j2 * 12 + ((j2 >> 6) << 2);
                *(float4*)(hT + d1)     = v0;
                *(float4*)(hT + d1 + 4) = v1;
                *(float4*)(hT + d2)     = v2;
                *(float4*)(hT + d2 + 4) = v3;
            }
            __syncthreads();
        }

        // prefetch next step's xg (hides under dot)
        float nxr = 0.f, nxz = 0.f, nxn = 0.f;
        if (t + 1 < T_STEPS) {
            const float* xp = xg + (size_t)(t + 1) * BATCH * GATES3 + xofs;
            nxr = __ldg(xp);
            nxz = __ldg(xp + HID);
            nxn = __ldg(xp + 2 * HID);
        }

        // dot: 3 gates x 8 batches (4 f32x2) over K=64
        float2 a00 = {0,0}, a01 = {0,0}, a02 = {0,0}, a03 = {0,0};
        float2 a10 = {0,0}, a11 = {0,0}, a12 = {0,0}, a13 = {0,0};
        float2 a20 = {0,0}, a21 = {0,0}, a22 = {0,0}, a23 = {0,0};
#pragma unroll 4
        for (int kl = 0; kl < 64; kl += 4) {
            float4 w_r = *(const float4*)(wp_r + kl);
            float4 w_z = *(const float4*)(wp_z + kl);
            float4 w_n = *(const float4*)(wp_n + kl);
#pragma unroll
            for (int i = 0; i < 4; ++i) {
                int ho = (kl + i) * 12;
                float4 hA = *(const float4*)(hbase + ho);      // batches 0..3
                float4 hB = *(const float4*)(hbase + ho + 4);  // batches 4..7
                float wr = (i == 0) ? w_r.x : (i == 1) ? w_r.y : (i == 2) ? w_r.z : w_r.w;
                float wz = (i == 0) ? w_z.x : (i == 1) ? w_z.y : (i == 2) ? w_z.z : w_z.w;
                float wn = (i == 0) ? w_n.x : (i == 1) ? w_n.y : (i == 2) ? w_n.z : w_n.w;
                float2 wr2 = make_float2(wr, wr);
                float2 wz2 = make_float2(wz, wz);
                float2 wn2 = make_float2(wn, wn);
                a00 = ffma2(wr2, make_float2(hA.x, hA.y), a00);
                a01 = ffma2(wr2, make_float2(hA.z, hA.w), a01);
                a02 = ffma2(wr2, make_float2(hB.x, hB.y), a02);
                a03 = ffma2(wr2, make_float2(hB.z, hB.w), a03);
                a10 = ffma2(wz2, make_float2(hA.x, hA.y), a10);
                a11 = ffma2(wz2, make_float2(hA.z, hA.w), a11);
                a12 = ffma2(wz2, make_float2(hB.x, hB.y), a12);
                a13 = ffma2(wz2, make_float2(hB.z, hB.w), a13);
                a20 = ffma2(wn2, make_float2(hA.x, hA.y), a20);
                a21 = ffma2(wn2, make_float2(hA.z, hA.w), a21);
                a22 = ffma2(wn2, make_float2(hB.x, hB.y), a22);
                a23 = ffma2(wn2, make_float2(hB.z, hB.w), a23);
            }
        }

        __syncthreads();   // all hT reads done before red overwrites it
        float2* red = (float2*)hT;
        {
            int base = (col * 12) * 8 + ks;   // idx(g,bp) = (col*12 + g*4 + bp)*8 + ks
            red[base +  0 * 8] = a00; red[base +  1 * 8] = a01;
            red[base +  2 * 8] = a02; red[base +  3 * 8] = a03;
            red[base +  4 * 8] = a10; red[base +  5 * 8] = a11;
            red[base +  6 * 8] = a12; red[base +  7 * 8] = a13;
            red[base +  8 * 8] = a20; red[base +  9 * 8] = a21;
            red[base + 10 * 8] = a22; red[base + 11 * 8] = a23;
        }
        __syncthreads();

        // gather: thread (col, bb) finalizes h[col, b0+bb]
        float hg[3];
        {
            int bp = bb >> 1;
#pragma unroll
            for (int g = 0; g < 3; ++g) {
                const float2* rp = red + (col * 12 + g * 4 + bp) * 8;
                float4 p0 = *(const float4*)(rp);
                float4 p1 = *(const float4*)(rp + 2);
                float4 p2 = *(const float4*)(rp + 4);
                float4 p3 = *(const float4*)(rp + 6);
                float se = p0.x + p0.z + p1.x + p1.z + p2.x + p2.z + p3.x + p3.z;
                float so = p0.y + p0.w + p1.y + p1.w + p2.y + p2.w + p3.y + p3.w;
                hg[g] = (bb & 1) ? so : se;
            }
        }
        float rg = sigmoidf_(xr + hg[0] + bhr);
        float zg = sigmoidf_(xz + hg[1] + bhz);
        float ng = tanhf(xn + rg * (hg[2] + bhn));
        hp = (1.f - zg) * ng + zg * hp;

        // publish h (transposed layout), then flag
        g_hxT[(size_t)((t + 1) & 1) * HID * BATCH + (size_t)j * BATCH + b] = hp;
        __syncthreads();
        if (tid == 0 && t < T_STEPS - 1) {
            __threadfence();
            asm volatile("st.global.cg.u32 [%0], %1;"
                         :: "l"(&g_flags[bid]), "r"((unsigned)(t + 1)) : "memory");
        }

        // off critical path
        y[((size_t)t * BATCH + b) * HID + j] = hp;
        if (t == T_STEPS - 1) hn_out[(size_t)b * HID + j] = hp;
        xr = nxr; xz = nxz; xn = nxn;
    }

    // end-of-launch: group gen-barrier (replay-safe), reset own flag
    __syncthreads();
    if (tid == 0) {
        unsigned gen = g_end_gen[grp];
        __threadfence();
        if (atomicAdd(&g_end_cnt[grp], 1u) == 15u) {
            g_end_cnt[grp] = 0u;
            __threadfence();
            g_end_gen[grp] = gen + 1u;
        } else {
            while (g_end_gen[grp] == gen) { __nanosleep(32); }
        }
        g_flags[bid] = 0u;
        __threadfence();
    }
}

// ---------------- launch ----------------
extern "C" void kernel_launch(void* const* d_in, const int* in_sizes, int n_in,
                              void* d_out, int out_size) {
    const float* x    = (const float*)d_in[0];
    const float* Wih0 = (const float*)d_in[1];
    const float* Whh0 = (const float*)d_in[2];
    const float* bih0 = (const float*)d_in[3];
    const float* bhh0 = (const float*)d_in[4];
    const float* Wih1 = (const float*)d_in[5];
    const float* Whh1 = (const float*)d_in[6];
    const float* bih1 = (const float*)d_in[7];
    const float* bhh1 = (const float*)d_in[8];

    float* out = (float*)d_out;
    float* y1  = out;
    float* hn0 = out + (size_t)T_STEPS * BATCH * HID;
    float* hn1 = hn0 + BATCH * HID;

    float *xg, *y0;
    cudaGetSymbolAddress((void**)&xg, g_xg);
    cudaGetSymbolAddress((void**)&y0, g_y0);

    const int rec_smem = (96 * WP + HT_SZ) * 4;  // 232,032 B
    cudaFuncSetAttribute(gru_rec_kernel, cudaFuncAttributeMaxDynamicSharedMemorySize, rec_smem);

    dim3 ggrid(12, 256);

    gemm_bias_kernel<<<ggrid, 256>>>(x, Wih0, bih0, xg, 256);
    gru_rec_kernel<<<NB_REC, NT_REC, rec_smem>>>(xg, Whh0, bhh0, y0, hn0);
    gemm_bias_kernel<<<ggrid, 256>>>(y0, Wih1, bih1, xg, 512);
    gru_rec_kernel<<<NB_REC, NT_REC, rec_smem>>>(xg, Whh1, bhh1, y1, hn1);
}